// round 10
// baseline (speedup 1.0000x reference)
#include <cuda_runtime.h>
#include <math.h>
#include <stdint.h>

typedef unsigned long long ull;

#define BB 256
#define HH 512
#define TT 512

#define CS 8        // cluster size (CTAs per cluster)
#define ROWS 64     // H rows per CTA
#define BT 16       // batch elems per cluster
#define NTH 512     // 16 warps, 4 per SMSP

// Output layout (flattened tuple: keys, prs, hs, tm_modified), float32
#define KEYS_OFF 0
#define PRS_OFF  (BB * 2 * TT)
#define HS_OFF   (PRS_OFF + BB * 4 * TT)
#define TM_OFF   (HS_OFF + (size_t)BB * HH * TT)

// Shared layout (float offsets)
#define OFF_WT   0                          // float [512][64]  W_rec^T slice (128 KB)
#define OFF_HB2  32768                      // ull   [512][16]  dup'd h       (64 KB)
#define OFF_RED  (OFF_HB2 + 16384)          // ull   [12][128]  k-split partials (12 KB)
#define OFF_WIN  (OFF_RED + 3072)           // float [6][64]    W_in^T slice
#define OFF_BIAS (OFF_WIN + 6 * ROWS)       // float [64]
#define OFF_WK   (OFF_BIAS + ROWS)          // float [2][512]
#define OFF_X    (OFF_WK + 2 * HH)          // float [16][8]
#define OFF_INPU (OFF_X + BT * 8)           // ull   [6][16]    dup'd inp
#define OFF_KEY  (OFF_INPU + 192)           // float [16]
#define OFF_BK   (OFF_KEY + BT)             // float [2] (+pad)
#define OFF_KP   (OFF_BK + 4)               // float [4][32]    key partials
#define SMEM_FLOATS (OFF_KP + 128)
#define SMEM_BYTES  (SMEM_FLOATS * 4)       // ~216.7 KB

// h scratch in [t][b][i] layout; t=0 slab zeroed by misc_kernel
__device__ float g_scr[(size_t)TT * BB * HH];
__device__ float g_key[BB];                 // key carry across split launches

__device__ __forceinline__ ull pack2(float x, float y) {
    ull r; asm("mov.b64 %0, {%1, %2};" : "=l"(r) : "f"(x), "f"(y)); return r;
}
__device__ __forceinline__ void unpack2(float& x, float& y, ull v) {
    asm("mov.b64 {%0, %1}, %2;" : "=f"(x), "=f"(y) : "l"(v));
}
__device__ __forceinline__ void ffma2(ull& d, ull a, ull b) {
    asm("fma.rn.f32x2 %0, %1, %2, %0;" : "+l"(d) : "l"(a), "l"(b));
}
__device__ __forceinline__ void fadd2(ull& d, ull a) {
    asm("add.rn.f32x2 %0, %0, %1;" : "+l"(d) : "l"(a));
}
__device__ __forceinline__ float ftanh(float x) {
    float e = __expf(2.f * x);
    return 1.f - __fdividef(2.f, e + 1.f);
}

// reload h(tt) for this cluster's 16 batches into dup'd smem.
// lanes span batch (rb) -> STS banks distinct (2-way conflict only).
__device__ __forceinline__ void reload_h(ull* sHb2, const float* src_base, int tid) {
    int rb = tid & 15, rc = (tid >> 4) & 15, rq = tid >> 8;   // rq 0/1
    const float* src = src_base + (size_t)rb * HH + rq * 256 + rc * 16;
    float4 v0 = ((const float4*)src)[0];
    float4 v1 = ((const float4*)src)[1];
    float4 v2 = ((const float4*)src)[2];
    float4 v3 = ((const float4*)src)[3];
    ull* dst = sHb2 + rb + ((rq * 256 + rc * 16) << 4);
    dst[0 << 4] = pack2(v0.x, v0.x);  dst[1 << 4] = pack2(v0.y, v0.y);
    dst[2 << 4] = pack2(v0.z, v0.z);  dst[3 << 4] = pack2(v0.w, v0.w);
    dst[4 << 4] = pack2(v1.x, v1.x);  dst[5 << 4] = pack2(v1.y, v1.y);
    dst[6 << 4] = pack2(v1.z, v1.z);  dst[7 << 4] = pack2(v1.w, v1.w);
    dst[8 << 4] = pack2(v2.x, v2.x);  dst[9 << 4] = pack2(v2.y, v2.y);
    dst[10 << 4] = pack2(v2.z, v2.z); dst[11 << 4] = pack2(v2.w, v2.w);
    dst[12 << 4] = pack2(v3.x, v3.x); dst[13 << 4] = pack2(v3.y, v3.y);
    dst[14 << 4] = pack2(v3.z, v3.z); dst[15 << 4] = pack2(v3.w, v3.w);
}

__global__ void __cluster_dims__(CS, 1, 1) __launch_bounds__(NTH, 1)
rnn_kernel(const float* __restrict__ xin,
           const float* __restrict__ Win,  const float* __restrict__ bin,
           const float* __restrict__ Wrec, const float* __restrict__ brec,
           const float* __restrict__ Wkey, const float* __restrict__ bkey,
           float* __restrict__ out, int t0, int nsteps)
{
    extern __shared__ float sm[];
    float* sWt   = sm + OFF_WT;
    ull*   sHb2  = (ull*)(sm + OFF_HB2);
    ull*   sRed  = (ull*)(sm + OFF_RED);
    float* sWin  = sm + OFF_WIN;
    float* sBias = sm + OFF_BIAS;
    float* sWk   = sm + OFF_WK;
    float* sX    = sm + OFF_X;
    ull*   sInpu = (ull*)(sm + OFF_INPU);
    float* sKey  = sm + OFF_KEY;
    float* sBk   = sm + OFF_BK;
    float* sKp   = sm + OFF_KP;

    const int tid  = threadIdx.x;
    const int rank = blockIdx.x & (CS - 1);
    const int cid  = blockIdx.x / CS;
    const int b0   = cid * BT;
    const int row0 = rank * ROWS;

    // ---- init (per launch) ----
    for (int idx = tid; idx < HH * ROWS; idx += NTH) {
        int r = idx & (ROWS - 1), k = idx >> 6;
        sWt[idx] = Wrec[(row0 + r) * HH + k];
    }
    for (int idx = tid; idx < 6 * ROWS; idx += NTH) {
        int r = idx & 63, j = idx >> 6;
        sWin[idx] = Win[(row0 + r) * 6 + j];
    }
    for (int idx = tid; idx < ROWS; idx += NTH)
        sBias[idx] = bin[row0 + idx] + brec[row0 + idx];
    for (int idx = tid; idx < 2 * HH; idx += NTH)
        sWk[idx] = Wkey[idx];
    if (tid < BT) sKey[tid] = g_key[b0 + tid];
    if (tid < 2)  sBk[tid]  = bkey[tid];
    __syncthreads();

    // preload h(t0-1) into dup'd smem
    reload_h(sHb2, g_scr + ((size_t)(t0 - 1) * BB + b0) * HH, tid);

    // GEMM thread decode: k-quarter, 4 rows x 2 batches
    const int kq  = tid >> 7;
    const int r   = tid & 127;
    const int tb2 = (r & 7) * 2;
    const int tr4 = (r >> 3) * 4;
    const int kbase = kq * 128;

    // x prefetch (one channel of one batch per thread, tid<128)
    const int xb = (tid >> 3) & 15, xc = tid & 7;
    const size_t xbase = ((size_t)(b0 + xb) * 8 + xc) * TT;
    float xr = (tid < 128) ? xin[xbase + t0] : 0.f;

    for (int s = 0; s < nsteps; s++) {
        const int t = t0 + s;

        if (tid < 128) sX[tid] = xr;
        __syncthreads();                                    // A

        if (tid < 16) {
            int b = tid;
            float kp = sKey[b];
            float a0 = sX[b * 8 + 0], a1 = sX[b * 8 + 1];
            float s0 = sX[b * 8 + 2], s1 = sX[b * 8 + 3];
            float s2 = sX[b * 8 + 4], s3 = sX[b * 8 + 5];
            float t0v = sX[b * 8 + 6], t1v = sX[b * 8 + 7];
            float m0 = s0 * kp + s2 * (1.f - kp);
            float m1 = s1 * kp + s3 * (1.f - kp);
            sInpu[0 * 16 + b] = pack2(a0, a0);
            sInpu[1 * 16 + b] = pack2(a1, a1);
            sInpu[2 * 16 + b] = pack2(m0, m0);
            sInpu[3 * 16 + b] = pack2(m1, m1);
            sInpu[4 * 16 + b] = pack2(t0v, t0v);
            sInpu[5 * 16 + b] = pack2(t1v, t1v);
            if (rank == 0) {
                float q0 = (t0v - a0) / (0.15f * a0); q0 *= q0; if (t0v == 0.f) q0 = 0.f;
                float q1 = (t0v - a1) / (0.15f * a1); q1 *= q1; if (t0v == 0.f) q1 = 0.f;
                float q2 = (t1v - m0) / (0.15f * m0); q2 *= q2; if (t1v == 0.f) q2 = 0.f;
                float q3 = (t1v - m1) / (0.15f * m1); q3 *= q3; if (t1v == 0.f) q3 = 0.f;
                float* p = out + PRS_OFF + (size_t)(b0 + b) * 4 * TT + t;
                p[0] = q0; p[TT] = q1; p[2 * TT] = q2; p[3 * TT] = q3;
            }
        }
        __syncthreads();                                    // B

        if (tid < 128 && s + 1 < nsteps) xr = xin[xbase + t + 1];

        // ---- GEMM: 2x LDS.128 + 4x fma.f32x2 per k ----
        ull A00, A10, A01, A11;
        if (kq == 0) {
            A00 = pack2(sBias[tr4], sBias[tr4 + 1]);
            A10 = pack2(sBias[tr4 + 2], sBias[tr4 + 3]);
            A01 = A00; A11 = A10;
            #pragma unroll
            for (int j = 0; j < 6; j++) {
                ulonglong2 w  = *(const ulonglong2*)(sWin + j * 64 + tr4);
                ulonglong2 hd = *(const ulonglong2*)(sInpu + j * 16 + tb2);
                ffma2(A00, w.x, hd.x); ffma2(A10, w.y, hd.x);
                ffma2(A01, w.x, hd.y); ffma2(A11, w.y, hd.y);
            }
        } else {
            A00 = A10 = A01 = A11 = 0ull;
        }
        {
            const float* Wp = sWt + tr4;
            const ull*   Hp = sHb2 + tb2;
            #pragma unroll 8
            for (int kk = 0; kk < 128; kk++) {
                int k = kbase + kk;
                ulonglong2 w  = *(const ulonglong2*)(Wp + (k << 6));
                ulonglong2 hd = *(const ulonglong2*)(Hp + (k << 4));
                ffma2(A00, w.x, hd.x); ffma2(A10, w.y, hd.x);
                ffma2(A01, w.x, hd.y); ffma2(A11, w.y, hd.y);
            }
        }
        if (kq >= 1) {
            ull* rp = sRed + (kq - 1) * 512 + r;
            rp[0] = A00; rp[128] = A10; rp[256] = A01; rp[384] = A11;
        }
        __syncthreads();                                    // C
        if (kq == 0) {
            #pragma unroll
            for (int p = 0; p < 3; p++) {
                const ull* rp = sRed + p * 512 + r;
                fadd2(A00, rp[0]); fadd2(A10, rp[128]);
                fadd2(A01, rp[256]); fadd2(A11, rp[384]);
            }
            float r0, r1, r2, r3;
            size_t base = ((size_t)t * BB + b0 + tb2) * HH + row0 + tr4;
            unpack2(r0, r1, A00); unpack2(r2, r3, A10);
            *(float4*)(g_scr + base) =
                make_float4(ftanh(r0), ftanh(r1), ftanh(r2), ftanh(r3));
            unpack2(r0, r1, A01); unpack2(r2, r3, A11);
            *(float4*)(g_scr + base + HH) =
                make_float4(ftanh(r0), ftanh(r1), ftanh(r2), ftanh(r3));
        }

        // ---- exchange h_t across cluster (release/acquire) ----
        asm volatile("barrier.cluster.arrive.aligned;" ::: "memory");
        asm volatile("barrier.cluster.wait.aligned;"   ::: "memory");

        reload_h(sHb2, g_scr + ((size_t)t * BB + b0) * HH, tid);
        __syncthreads();                                    // D

        // ---- keys: 32 dots, 4 warps x 128 terms each, 4 chains ----
        if (tid < 128) {
            int l = tid >> 5, dg = tid & 31;
            int b = dg >> 1, o = dg & 1;
            const float* wk = sWk + o * HH;
            const float* hv = (const float*)sHb2;   // dup'd: h at [(k*16+b)*2]
            float p0 = 0.f, p1 = 0.f, p2 = 0.f, p3 = 0.f;
            #pragma unroll 8
            for (int m = 0; m < 128; m += 4) {
                int k0 = l + m * 4;
                p0 = fmaf(wk[k0],      hv[(k0 * 16 + b) * 2],        p0);
                p1 = fmaf(wk[k0 + 4],  hv[((k0 + 4) * 16 + b) * 2],  p1);
                p2 = fmaf(wk[k0 + 8],  hv[((k0 + 8) * 16 + b) * 2],  p2);
                p3 = fmaf(wk[k0 + 12], hv[((k0 + 12) * 16 + b) * 2], p3);
            }
            sKp[l * 32 + dg] = (p0 + p1) + (p2 + p3);
        }
        __syncthreads();                                    // F
        if (tid < 32) {
            int dg = tid, b = dg >> 1, o = dg & 1;
            float sum = sKp[dg] + sKp[32 + dg] + sKp[64 + dg] + sKp[96 + dg] + sBk[o];
            float kv = __fdividef(1.f, 1.f + __expf(-sum));
            if (o == 0) sKey[b] = kv;
            if (rank == 0) {
                out[KEYS_OFF + (size_t)(b0 + b) * 2 * TT + o * TT + t] = kv;
                if (o == 0 && s == nsteps - 1) g_key[b0 + b] = kv;
            }
        }
        // next iteration's barrier A orders sKey/sX hazards
    }
}

// Zero t=0 planes (scratch slab, keys, prs), init key carry, copy tm_modified.
__global__ void misc_kernel(const float* __restrict__ xin, float* __restrict__ out)
{
    int idx = blockIdx.x * blockDim.x + threadIdx.x;
    if (idx < BB * HH) g_scr[idx] = 0.f;
    if (idx < BB)      g_key[idx] = 1.f;
    if (idx < BB * 2)  out[KEYS_OFF + (idx >> 1) * (2 * TT) + (idx & 1) * TT] = 0.f;
    if (idx < BB * 4)  out[PRS_OFF + (idx >> 2) * (4 * TT) + (idx & 3) * TT] = 0.f;
    if (idx < BB * 2 * TT) {
        int b = idx >> 10, rr = idx & 1023;
        out[TM_OFF + idx] = xin[(size_t)b * 8 * TT + 6 * TT + rr];
    }
}

// Transpose scratch [t][b][i] -> hs (b, i, t), 32x32 tiles.
__global__ void transpose_kernel(float* __restrict__ out)
{
    __shared__ float tile[32][33];
    int b  = blockIdx.z;
    int i0 = blockIdx.y * 32;
    int t0 = blockIdx.x * 32;
    int tx = threadIdx.x, ty = threadIdx.y;
    #pragma unroll
    for (int j = 0; j < 32; j += 8)
        tile[ty + j][tx] =
            g_scr[(size_t)(t0 + ty + j) * BB * HH + (size_t)b * HH + i0 + tx];
    __syncthreads();
    float* dst = out + HS_OFF + (size_t)b * HH * TT;
    #pragma unroll
    for (int j = 0; j < 32; j += 8)
        dst[(size_t)(i0 + ty + j) * TT + t0 + tx] = tile[tx][ty + j];
}

extern "C" void kernel_launch(void* const* d_in, const int* in_sizes, int n_in,
                              void* d_out, int out_size)
{
    const float* xin  = (const float*)d_in[0];
    const float* Win  = (const float*)d_in[1];
    const float* bin  = (const float*)d_in[2];
    const float* Wrec = (const float*)d_in[3];
    const float* brec = (const float*)d_in[4];
    const float* Wkey = (const float*)d_in[5];
    const float* bkey = (const float*)d_in[6];
    float* out = (float*)d_out;

    cudaFuncSetAttribute(rnn_kernel,
                         cudaFuncAttributeMaxDynamicSharedMemorySize, SMEM_BYTES);

    misc_kernel<<<1024, 256>>>(xin, out);
    // split into 2 launches (t in [1,256) and [256,512)) — carry via g_scr/g_key
    rnn_kernel<<<(BB / BT) * CS, NTH, SMEM_BYTES>>>(xin, Win, bin, Wrec, brec,
                                                    Wkey, bkey, out, 1, 255);
    rnn_kernel<<<(BB / BT) * CS, NTH, SMEM_BYTES>>>(xin, Win, bin, Wrec, brec,
                                                    Wkey, bkey, out, 256, 256);
    dim3 g(TT / 32, HH / 32, BB), blk(32, 8);
    transpose_kernel<<<g, blk>>>(out);
}